// round 14
// baseline (speedup 1.0000x reference)
#include <cuda_runtime.h>

#define N_PATHS   8
#define N_FEAT    128
#define CART      3
#define N_SPECIES 10
#define ROW_F4    1024          // 4096 floats per x row = 1024 float4
#define OUT_F4    96            // 384 floats per out row = 96 float4
#define TPB       384           // 12 warps = 4 atom-slots of 96 lanes
#define SLOTS     4             // atom slots per CTA
#define LPA       96            // lanes per atom (3 full warps per atom)

__global__ __launch_bounds__(TPB, 2)   // 85-reg cap: 16 in-flight float4 + accs
void wps_kernel(const float4* __restrict__ x,
                const float*  __restrict__ y,
                const float*  __restrict__ w,
                float4* __restrict__ out,
                int n_atoms)
{
    const int slot = threadIdx.x / LPA;    // 0..3
    const int lane = threadIdx.x % LPA;    // 0..95
    const int wl   = threadIdx.x & 31;

    const int e0 = lane * 4;
    const int f0 = e0 / CART;
    const int r  = e0 - f0 * CART;         // e0 % 3

    const int stride  = gridDim.x * SLOTS;
    const int stride2 = 2 * stride;

    int a = blockIdx.x * SLOTS + slot;

    // ---- main loop: 2 atoms per iteration, ALL 16 loads front-batched ----
    for (; a + stride < n_atoms; a += stride2) {
        const int a0 = a, a1 = a + stride;
        const float4* x0 = x + (size_t)a0 * ROW_F4;
        const float4* x1 = x + (size_t)a1 * ROW_F4;

        // PHASE 1: issue all 16 x loads (8 KB in flight per warp)
        float4 xv0[N_PATHS], xv1[N_PATHS];
        #pragma unroll
        for (int p = 0; p < N_PATHS; ++p)
            xv0[p] = __ldcs(&x0[p * LPA + lane]);
        #pragma unroll
        for (int p = 0; p < N_PATHS; ++p)
            xv1[p] = __ldcs(&x1[p * LPA + lane]);

        // species decodes overlap with the in-flight x loads
        float yv0 = (wl < N_SPECIES) ? __ldcs(&y[(size_t)a0 * N_SPECIES + wl]) : 0.0f;
        float yv1 = (wl < N_SPECIES) ? __ldcs(&y[(size_t)a1 * N_SPECIES + wl]) : 0.0f;
        const int s0 = __ffs(__ballot_sync(0xffffffffu, yv0 > 0.5f)) - 1;
        const int s1 = __ffs(__ballot_sync(0xffffffffu, yv1 > 0.5f)) - 1;

        const float* w0 = w + s0 * (N_PATHS * N_FEAT) + f0;
        const float* w1 = w + s1 * (N_PATHS * N_FEAT) + f0;

        // PHASE 2: FMA drain for both atoms
        float4 acc0 = {0.f, 0.f, 0.f, 0.f};
        float4 acc1 = {0.f, 0.f, 0.f, 0.f};
        #pragma unroll
        for (int p = 0; p < N_PATHS; ++p) {
            float wa0 = __ldg(&w0[p * N_FEAT]);
            float wb0 = __ldg(&w0[p * N_FEAT + 1]);
            float wy0 = (r == 2) ? wb0 : wa0;
            float wz0 = (r == 0) ? wa0 : wb0;
            acc0.x = fmaf(xv0[p].x, wa0, acc0.x);
            acc0.y = fmaf(xv0[p].y, wy0, acc0.y);
            acc0.z = fmaf(xv0[p].z, wz0, acc0.z);
            acc0.w = fmaf(xv0[p].w, wb0, acc0.w);
        }
        #pragma unroll
        for (int p = 0; p < N_PATHS; ++p) {
            float wa1 = __ldg(&w1[p * N_FEAT]);
            float wb1 = __ldg(&w1[p * N_FEAT + 1]);
            float wy1 = (r == 2) ? wb1 : wa1;
            float wz1 = (r == 0) ? wa1 : wb1;
            acc1.x = fmaf(xv1[p].x, wa1, acc1.x);
            acc1.y = fmaf(xv1[p].y, wy1, acc1.y);
            acc1.z = fmaf(xv1[p].z, wz1, acc1.z);
            acc1.w = fmaf(xv1[p].w, wb1, acc1.w);
        }

        __stcs(&out[(size_t)a0 * OUT_F4 + lane], acc0);
        __stcs(&out[(size_t)a1 * OUT_F4 + lane], acc1);
    }

    // ---- tail: single remaining atom ----
    if (a < n_atoms) {
        const float4* xrow = x + (size_t)a * ROW_F4;
        float4 xv[N_PATHS];
        #pragma unroll
        for (int p = 0; p < N_PATHS; ++p)
            xv[p] = __ldcs(&xrow[p * LPA + lane]);

        float yv = (wl < N_SPECIES) ? __ldcs(&y[(size_t)a * N_SPECIES + wl]) : 0.0f;
        const int s = __ffs(__ballot_sync(0xffffffffu, yv > 0.5f)) - 1;
        const float* wsp = w + s * (N_PATHS * N_FEAT) + f0;

        float4 acc = {0.f, 0.f, 0.f, 0.f};
        #pragma unroll
        for (int p = 0; p < N_PATHS; ++p) {
            float wa = __ldg(&wsp[p * N_FEAT]);
            float wb = __ldg(&wsp[p * N_FEAT + 1]);
            float wy = (r == 2) ? wb : wa;
            float wz = (r == 0) ? wa : wb;
            acc.x = fmaf(xv[p].x, wa, acc.x);
            acc.y = fmaf(xv[p].y, wy, acc.y);
            acc.z = fmaf(xv[p].z, wz, acc.z);
            acc.w = fmaf(xv[p].w, wb, acc.w);
        }
        __stcs(&out[(size_t)a * OUT_F4 + lane], acc);
    }
}

extern "C" void kernel_launch(void* const* d_in, const int* in_sizes, int n_in,
                              void* d_out, int out_size)
{
    const float4* x = (const float4*)d_in[0];   // [N, 4096] fp32
    const float*  y = (const float*) d_in[1];   // [N, 10] one-hot
    const float*  w = (const float*) d_in[2];   // [10, 8, 128] fp32
    float4* out = (float4*)d_out;               // [N, 384] fp32

    const int n_atoms = in_sizes[0] / 4096;

    int grid = 148 * 2;                          // 2 CTAs/SM, deep-batch config
    int max_grid = (n_atoms + SLOTS - 1) / SLOTS;
    if (grid > max_grid) grid = max_grid;

    wps_kernel<<<grid, TPB>>>(x, y, w, out, n_atoms);
}

// round 15
// speedup vs baseline: 1.0247x; 1.0247x over previous
#include <cuda_runtime.h>

#define N_PATHS   8
#define N_FEAT    128
#define CART      3
#define N_SPECIES 10
#define ROW_F4    1024          // 4096 floats per x row = 1024 float4
#define OUT_F4    96            // 384 floats per out row = 96 float4
#define TPB       384           // 12 warps = 4 atom-slots of 96 lanes
#define SLOTS     4             // atoms per CTA per iteration
#define LPA       96            // lanes per atom (3 full warps per atom)

__global__ __launch_bounds__(TPB, 3)   // 56-reg cap: room for 8 in-flight float4
void wps_kernel(const float4* __restrict__ x,
                const float*  __restrict__ y,
                const float*  __restrict__ w,
                float4* __restrict__ out,
                int n_atoms)
{
    const int slot = threadIdx.x / LPA;    // 0..3 : which atom in the group
    const int lane = threadIdx.x % LPA;    // 0..95: which float4 of the output
    const int wl   = threadIdx.x & 31;     // lane within warp

    // the 4 output elements e = 4*lane .. 4*lane+3 span exactly 2 features
    const int e0 = lane * 4;
    const int f0 = e0 / CART;              // first feature
    const int r  = e0 - f0 * CART;         // e0 % 3, fixed per thread

    const int stride_atoms = gridDim.x * SLOTS;

    for (int a = blockIdx.x * SLOTS + slot; a < n_atoms; a += stride_atoms) {
        const float4* xrow = x + (size_t)a * ROW_F4;

        // ---- PHASE 1: front-batch ALL 8 x loads (4 KB in flight per warp) ----
        float4 xv[N_PATHS];
        #pragma unroll
        for (int p = 0; p < N_PATHS; ++p)
            xv[p] = __ldcs(&xrow[p * LPA + lane]);   // streaming read-once

        // ---- species via warp ballot (overlaps with in-flight x loads) ----
        const float* yrow = y + (size_t)a * N_SPECIES;
        float yv = (wl < N_SPECIES) ? __ldcs(&yrow[wl]) : 0.0f;
        unsigned m = __ballot_sync(0xffffffffu, yv > 0.5f);
        const int s = __ffs(m) - 1;

        const float* wsp = w + s * (N_PATHS * N_FEAT) + f0;  // 40 KB, L1-resident

        // ---- PHASE 2: FMA drain ----
        float4 acc = {0.f, 0.f, 0.f, 0.f};
        #pragma unroll
        for (int p = 0; p < N_PATHS; ++p) {
            float wa = __ldg(&wsp[p * N_FEAT]);
            float wb = __ldg(&wsp[p * N_FEAT + 1]);
            // r=0: (wa,wa,wa,wb)  r=1: (wa,wa,wb,wb)  r=2: (wa,wb,wb,wb)
            float wy = (r == 2) ? wb : wa;
            float wz = (r == 0) ? wa : wb;
            acc.x = fmaf(xv[p].x, wa, acc.x);
            acc.y = fmaf(xv[p].y, wy, acc.y);
            acc.z = fmaf(xv[p].z, wz, acc.z);
            acc.w = fmaf(xv[p].w, wb, acc.w);
        }

        __stcs(&out[(size_t)a * OUT_F4 + lane], acc);
    }
}

extern "C" void kernel_launch(void* const* d_in, const int* in_sizes, int n_in,
                              void* d_out, int out_size)
{
    const float4* x = (const float4*)d_in[0];   // [N, 4096] fp32
    const float*  y = (const float*) d_in[1];   // [N, 10] one-hot
    const float*  w = (const float*) d_in[2];   // [10, 8, 128] fp32
    float4* out = (float4*)d_out;               // [N, 384] fp32

    const int n_atoms = in_sizes[0] / 4096;

    int grid = 148 * 3;                          // 3 CTAs/SM, even placement
    int max_grid = (n_atoms + SLOTS - 1) / SLOTS;
    if (grid > max_grid) grid = max_grid;

    wps_kernel<<<grid, TPB>>>(x, y, w, out, n_atoms);
}